// round 15
// baseline (speedup 1.0000x reference)
#include <cuda_runtime.h>
#include <cstdint>
#include <cstddef>

#define Nn 50000
#define Ee 1600000
#define Gg 128
#define Hh 64

// ---- scratch (device globals) ----
__device__ uint32_t g_z[(size_t)5 * Nn * Hh]; // 64 MB: z_k as tf32 bits
__device__ float g_h0[(size_t)Nn * Hh];        // ping
__device__ float g_h1[(size_t)Nn * Hh];        // pong
__device__ float g_pool[Gg * 2 * Hh];

// dst-CSR sort scratch (24 B/edge, split)
__device__ int    g_cnt[Nn];
__device__ int    g_cursor[Nn];
__device__ int    g_rowptr[Nn + 1];
__device__ float4 g_er0[Ee];                   // {src, w0, w1, w2}
__device__ float2 g_er1[Ee];                   // {w3, w4}

__device__ __forceinline__ uint32_t to_tf32(float v)
{
    uint32_t u;
    asm("cvt.rna.tf32.f32 %0, %1;" : "=r"(u) : "f"(v));
    return u;
}

// ============================================================
// counting sort by dst: hist -> scan -> permute
// ============================================================
__global__ void zero_cnt_kernel(int* __restrict__ cnt)
{
    unsigned i = blockIdx.x * 256u + threadIdx.x;
    if (i < (unsigned)Nn) cnt[i] = 0;
}

__global__ void hist_kernel(const int* __restrict__ ei, int* __restrict__ cnt)
{
    unsigned e = blockIdx.x * 256u + threadIdx.x;
    if (e < (unsigned)Ee) atomicAdd(&cnt[__ldg(ei + Ee + e)], 1);  // dst
}

__global__ void scan_kernel(const int* __restrict__ cnt,
                            int* __restrict__ cursor,
                            int* __restrict__ rowptr)
{
    __shared__ int tsum[1024];
    const int t  = threadIdx.x;
    const int CH = (Nn + 1023) / 1024;  // 49
    const int base = t * CH;

    int s = 0;
#pragma unroll 1
    for (int i = 0; i < CH; ++i) {
        int idx = base + i;
        if (idx < Nn) s += cnt[idx];
    }
    tsum[t] = s;
    __syncthreads();
    for (int o = 1; o < 1024; o <<= 1) {
        int u = (t >= o) ? tsum[t - o] : 0;
        __syncthreads();
        tsum[t] += u;
        __syncthreads();
    }
    int run = tsum[t] - s;  // exclusive
#pragma unroll 1
    for (int i = 0; i < CH; ++i) {
        int idx = base + i;
        if (idx < Nn) {
            cursor[idx] = run;
            rowptr[idx] = run;
            run += cnt[idx];
        }
    }
    if (t == 0) rowptr[Nn] = Ee;
}

__global__ void permute_kernel(const int* __restrict__ ei,
                               const float* __restrict__ ea,
                               int* __restrict__ cursor,
                               float4* __restrict__ er0,
                               float2* __restrict__ er1)
{
    unsigned e = blockIdx.x * 256u + threadIdx.x;
    if (e >= (unsigned)Ee) return;
    int src = __ldg(ei + e);
    int dst = __ldg(ei + Ee + e);
    const float* p = ea + (size_t)e * 5;
    float w0 = __ldg(p), w1 = __ldg(p + 1), w2 = __ldg(p + 2),
          w3 = __ldg(p + 3), w4 = __ldg(p + 4);
    int pos = atomicAdd(&cursor[dst], 1);
    er0[pos] = make_float4(__int_as_float(src), w0, w1, w2);
    er1[pos] = make_float2(w3, w4);
}

// ============================================================
// Aggregate (H=64): one warp per dst node; 2 edges in flight.
// Epilogue converts accumulators to tf32 bits for the MMA gemm.
// ============================================================
__global__ void aggregate64_kernel(const int* __restrict__ rowptr,
                                   const float4* __restrict__ er0,
                                   const float2* __restrict__ er1,
                                   const float* __restrict__ x,
                                   uint32_t* __restrict__ z)
{
    int dst = blockIdx.x * 8 + (threadIdx.x >> 5);
    if (dst >= Nn) return;
    const int lane = threadIdx.x & 31;
    const int hl   = lane & 15;   // feat group: feats 4*hl..4*hl+3
    const int par  = lane >> 4;   // edge parity
    const int beg = __ldg(rowptr + dst);
    const int end = __ldg(rowptr + dst + 1);

    float4 a0 = {0.f,0.f,0.f,0.f}, a1 = a0, a2 = a0, a3 = a0, a4 = a0;

#pragma unroll 2
    for (int e = beg + par; e < end; e += 2) {
        float4 r0 = __ldg(er0 + e);
        float2 r1 = __ldg(er1 + e);
        int src = __float_as_int(r0.x);
        float4 v = __ldg((const float4*)(x + (size_t)src * 64 + hl * 4));
        a0.x += r0.y*v.x; a0.y += r0.y*v.y; a0.z += r0.y*v.z; a0.w += r0.y*v.w;
        a1.x += r0.z*v.x; a1.y += r0.z*v.y; a1.z += r0.z*v.z; a1.w += r0.z*v.w;
        a2.x += r0.w*v.x; a2.y += r0.w*v.y; a2.z += r0.w*v.z; a2.w += r0.w*v.w;
        a3.x += r1.x*v.x; a3.y += r1.x*v.y; a3.z += r1.x*v.z; a3.w += r1.x*v.w;
        a4.x += r1.y*v.x; a4.y += r1.y*v.y; a4.z += r1.y*v.z; a4.w += r1.y*v.w;
    }

#define CMB(f) f += __shfl_xor_sync(0xffffffffu, f, 16)
    CMB(a0.x); CMB(a0.y); CMB(a0.z); CMB(a0.w);
    CMB(a1.x); CMB(a1.y); CMB(a1.z); CMB(a1.w);
    CMB(a2.x); CMB(a2.y); CMB(a2.z); CMB(a2.w);
    CMB(a3.x); CMB(a3.y); CMB(a3.z); CMB(a3.w);
    CMB(a4.x); CMB(a4.y); CMB(a4.z); CMB(a4.w);
#undef CMB

    if (par == 0) {
        const size_t KS = (size_t)Nn * 64;
        uint32_t* zp = z + (size_t)dst * 64 + hl * 4;
#define STT(off, a) { uint4 q; q.x = to_tf32(a.x); q.y = to_tf32(a.y); \
                      q.z = to_tf32(a.z); q.w = to_tf32(a.w); \
                      *(uint4*)(zp + (off)) = q; }
        STT(0,      a0)
        STT(KS,     a1)
        STT(2 * KS, a2)
        STT(3 * KS, a3)
        STT(4 * KS, a4)
#undef STT
    }
}

// ============================================================
// Aggregate (F=16, layer 1, raw x)
// ============================================================
__global__ void aggregate16_kernel(const int* __restrict__ rowptr,
                                   const float4* __restrict__ er0,
                                   const float2* __restrict__ er1,
                                   const float* __restrict__ x,
                                   uint32_t* __restrict__ z)
{
    int dst = blockIdx.x * 8 + (threadIdx.x >> 5);
    if (dst >= Nn) return;
    const int lane = threadIdx.x & 31;
    const int half = lane >> 4;
    const int f    = lane & 15;
    const int beg = __ldg(rowptr + dst);
    const int end = __ldg(rowptr + dst + 1);

    float a0 = 0.f, a1 = 0.f, a2 = 0.f, a3 = 0.f, a4 = 0.f;

    for (int e = beg + half; e < end; e += 2) {
        float4 r0 = __ldg(er0 + e);
        float2 r1 = __ldg(er1 + e);
        int src = __float_as_int(r0.x);
        float v = __ldg(x + (size_t)src * 16 + f);
        a0 += r0.y * v; a1 += r0.z * v; a2 += r0.w * v;
        a3 += r1.x * v; a4 += r1.y * v;
    }
    a0 += __shfl_xor_sync(0xffffffffu, a0, 16);
    a1 += __shfl_xor_sync(0xffffffffu, a1, 16);
    a2 += __shfl_xor_sync(0xffffffffu, a2, 16);
    a3 += __shfl_xor_sync(0xffffffffu, a3, 16);
    a4 += __shfl_xor_sync(0xffffffffu, a4, 16);

    if (half == 0) {
        const size_t KS = (size_t)Nn * 16;
        uint32_t* zp = z + (size_t)dst * 16 + f;
        zp[0]    = to_tf32(a0);
        zp[KS]   = to_tf32(a1);
        zp[2*KS] = to_tf32(a2);
        zp[3*KS] = to_tf32(a3);
        zp[4*KS] = to_tf32(a4);
    }
}

// ============================================================
// Tensor-core GEMM-sum: h[n] = relu( sum_k z_k[n] @ W[k] + b )
// mma.sync.m16n8k8 tf32. 128 nodes x 64 cols / CTA, 8 warps,
// warp tile 32x32. A fragments loaded DIRECTLY from global z
// (pre-converted tf32 bits, no cross-warp reuse -> no staging);
// only W staged in smem (cross-warp reuse). smem = KD*72*4.
// ============================================================
template<int KD>
__global__ void __launch_bounds__(256)
gemmsum_kernel(const uint32_t* __restrict__ zq,
               const float* __restrict__ W,
               const float* __restrict__ b,
               float* __restrict__ h)
{
    constexpr int WPAD = 72;
    extern __shared__ uint32_t smu[];
    uint32_t* ws = smu;                 // [KD][WPAD] tf32 bits

    const int t    = threadIdx.x;
    const int warp = t >> 5;
    const int lane = t & 31;
    const int gid  = lane >> 2;    // 0..7
    const int tig  = lane & 3;     // 0..3
    const int wm   = warp >> 1;    // 0..3 -> m offset 32*wm
    const int wn   = warp & 1;     // 0..1 -> n offset 32*wn
    const int n0   = blockIdx.x * 128;

    // this warp's two A row bases (node indices)
    const int r0 = n0 + wm * 32 + gid;        // mf=0 rows: r0, r0+8
    const int r1 = r0 + 16;                   // mf=1 rows: r1, r1+8

    float acc[2][4][4];
#pragma unroll
    for (int mf = 0; mf < 2; ++mf)
#pragma unroll
        for (int nf = 0; nf < 4; ++nf)
#pragma unroll
            for (int r = 0; r < 4; ++r) acc[mf][nf][r] = 0.f;

#pragma unroll 1
    for (int k = 0; k < 5; ++k) {
        __syncthreads();
        for (int idx = t; idx < KD * 64; idx += 256) {
            float v = __ldg(W + k * KD * 64 + idx);
            int kk = idx >> 6;
            int c  = idx & 63;
            ws[kk * WPAD + c] = to_tf32(v);
        }
        __syncthreads();

        const uint32_t* zk = zq + (size_t)k * Nn * KD;
#pragma unroll 4
        for (int kb = 0; kb < KD; kb += 8) {
            uint32_t a[2][4];
#pragma unroll
            for (int mf = 0; mf < 2; ++mf) {
                int ra = (mf == 0) ? r0 : r1;
                int rb = ra + 8;
                const uint32_t* pa = zk + (size_t)ra * KD + kb + tig;
                const uint32_t* pb = zk + (size_t)rb * KD + kb + tig;
                a[mf][0] = (ra < Nn) ? __ldg(pa)     : 0u;
                a[mf][1] = (rb < Nn) ? __ldg(pb)     : 0u;
                a[mf][2] = (ra < Nn) ? __ldg(pa + 4) : 0u;
                a[mf][3] = (rb < Nn) ? __ldg(pb + 4) : 0u;
            }
            uint32_t bf[4][2];
#pragma unroll
            for (int nf = 0; nf < 4; ++nf) {
                int col = wn * 32 + nf * 8 + gid;
                bf[nf][0] = ws[(kb + tig) * WPAD + col];
                bf[nf][1] = ws[(kb + tig + 4) * WPAD + col];
            }
#pragma unroll
            for (int mf = 0; mf < 2; ++mf)
#pragma unroll
                for (int nf = 0; nf < 4; ++nf) {
                    asm volatile(
                        "mma.sync.aligned.m16n8k8.row.col.f32.tf32.tf32.f32 "
                        "{%0,%1,%2,%3}, {%4,%5,%6,%7}, {%8,%9}, {%0,%1,%2,%3};"
                        : "+f"(acc[mf][nf][0]), "+f"(acc[mf][nf][1]),
                          "+f"(acc[mf][nf][2]), "+f"(acc[mf][nf][3])
                        : "r"(a[mf][0]), "r"(a[mf][1]), "r"(a[mf][2]), "r"(a[mf][3]),
                          "r"(bf[nf][0]), "r"(bf[nf][1]));
                }
        }
    }

    // epilogue: bias + relu + store
#pragma unroll
    for (int mf = 0; mf < 2; ++mf) {
#pragma unroll
        for (int nf = 0; nf < 4; ++nf) {
            int col = wn * 32 + nf * 8 + 2 * tig;
            float bx = __ldg(b + col);
            float by = __ldg(b + col + 1);
            int row = n0 + wm * 32 + mf * 16 + gid;
            if (row < Nn) {
                float2 o;
                o.x = fmaxf(acc[mf][nf][0] + bx, 0.f);
                o.y = fmaxf(acc[mf][nf][1] + by, 0.f);
                *(float2*)&h[(size_t)row * 64 + col] = o;
            }
            int row2 = row + 8;
            if (row2 < Nn) {
                float2 o;
                o.x = fmaxf(acc[mf][nf][2] + bx, 0.f);
                o.y = fmaxf(acc[mf][nf][3] + by, 0.f);
                *(float2*)&h[(size_t)row2 * 64 + col] = o;
            }
        }
    }
}

// ============================================================
// Pooling: h already relu'd; sum & max per analytic graph ranges.
// ============================================================
__global__ void pool_kernel(const float* __restrict__ h, float* __restrict__ pooled)
{
    __shared__ float ss[4][64];
    __shared__ float sm[4][64];
    int g     = blockIdx.x;
    int f     = threadIdx.x & 63;
    int strip = threadIdx.x >> 6;
    int start = (g * Nn + Gg - 1) / Gg;
    int end   = ((g + 1) * Nn + Gg - 1) / Gg;

    float s = 0.f, m = 0.f;  // h >= 0
    for (int n = start + strip; n < end; n += 4) {
        float v = __ldg(h + (size_t)n * 64 + f);
        s += v;
        m = fmaxf(m, v);
    }
    ss[strip][f] = s;
    sm[strip][f] = m;
    __syncthreads();
    if (strip == 0) {
        s = ss[0][f] + ss[1][f] + ss[2][f] + ss[3][f];
        m = fmaxf(fmaxf(sm[0][f], sm[1][f]), fmaxf(sm[2][f], sm[3][f]));
        pooled[g * 128 + f]      = s;
        pooled[g * 128 + 64 + f] = m;
    }
}

// ============================================================
// Head: BN -> FC -> log_softmax
// ============================================================
__global__ void head_kernel(const float* __restrict__ pooled,
                            const float* __restrict__ gam,
                            const float* __restrict__ bet,
                            const float* __restrict__ mean,
                            const float* __restrict__ var,
                            const float* __restrict__ fw,
                            const float* __restrict__ fb,
                            float* __restrict__ out)
{
    int g    = blockIdx.x;
    int lane = threadIdx.x;

    float pn[4];
#pragma unroll
    for (int i = 0; i < 4; ++i) {
        int c = lane + 32 * i;
        float p = __ldg(pooled + g * 128 + c);
        float inv = 1.f / sqrtf(__ldg(var + c) + 1e-5f);
        pn[i] = (p - __ldg(mean + c)) * inv * __ldg(gam + c) + __ldg(bet + c);
    }

    float logits[6];
#pragma unroll
    for (int j = 0; j < 6; ++j) {
        float s = 0.f;
#pragma unroll
        for (int i = 0; i < 4; ++i)
            s += pn[i] * __ldg(fw + (lane + 32 * i) * 6 + j);
#pragma unroll
        for (int o = 16; o; o >>= 1)
            s += __shfl_xor_sync(0xffffffffu, s, o);
        logits[j] = s + __ldg(fb + j);
    }

    if (lane == 0) {
        float m = logits[0];
#pragma unroll
        for (int j = 1; j < 6; ++j) m = fmaxf(m, logits[j]);
        float se = 0.f;
#pragma unroll
        for (int j = 0; j < 6; ++j) se += expf(logits[j] - m);
        float lse = m + logf(se);
#pragma unroll
        for (int j = 0; j < 6; ++j) out[g * 6 + j] = logits[j] - lse;
    }
}

// ============================================================
extern "C" void kernel_launch(void* const* d_in, const int* in_sizes, int n_in,
                              void* d_out, int out_size)
{
    const float* x   = (const float*)d_in[0];
    const int*   ei  = (const int*)  d_in[1];
    const float* ea  = (const float*)d_in[2];
    const float* W1  = (const float*)d_in[4];
    const float* b1  = (const float*)d_in[5];
    const float* W2  = (const float*)d_in[6];
    const float* b2  = (const float*)d_in[7];
    const float* W3  = (const float*)d_in[8];
    const float* b3  = (const float*)d_in[9];
    const float* W4  = (const float*)d_in[10];
    const float* b4  = (const float*)d_in[11];
    const float* bng = (const float*)d_in[12];
    const float* bnb = (const float*)d_in[13];
    const float* bnm = (const float*)d_in[14];
    const float* bnv = (const float*)d_in[15];
    const float* fw  = (const float*)d_in[16];
    const float* fb  = (const float*)d_in[17];
    float* out = (float*)d_out;

    uint32_t* zb;
    float *h0, *h1, *pl;
    int *cnt, *cur, *rp;
    float4* er0;
    float2* er1;
    cudaGetSymbolAddress((void**)&zb, g_z);
    cudaGetSymbolAddress((void**)&h0, g_h0);
    cudaGetSymbolAddress((void**)&h1, g_h1);
    cudaGetSymbolAddress((void**)&pl, g_pool);
    cudaGetSymbolAddress((void**)&cnt, g_cnt);
    cudaGetSymbolAddress((void**)&cur, g_cursor);
    cudaGetSymbolAddress((void**)&rp, g_rowptr);
    cudaGetSymbolAddress((void**)&er0, g_er0);
    cudaGetSymbolAddress((void**)&er1, g_er1);

    const int EB = (Ee + 255) / 256;        // 6250
    const int GB = (Nn + 127) / 128;        // 391
    const int AB = (Nn + 7) / 8;            // 6250 (one warp per dst)

    const int SM16 = 16 * 72 * 4;   // 4608 B
    const int SM64 = 64 * 72 * 4;   // 18432 B

    // ---- counting sort of edges by dst -> CSR ----
    zero_cnt_kernel<<<(Nn + 255) / 256, 256>>>(cnt);
    hist_kernel<<<EB, 256>>>(ei, cnt);
    scan_kernel<<<1, 1024>>>(cnt, cur, rp);
    permute_kernel<<<EB, 256>>>(ei, ea, cur, er0, er1);

    // ---- layer 1 (in: x [N,16], raw) ----
    aggregate16_kernel<<<AB, 256>>>(rp, er0, er1, x, zb);
    gemmsum_kernel<16><<<GB, 256, SM16>>>(zb, W1, b1, h0);
    // ---- layer 2 ----
    aggregate64_kernel<<<AB, 256>>>(rp, er0, er1, h0, zb);
    gemmsum_kernel<64><<<GB, 256, SM64>>>(zb, W2, b2, h1);
    // ---- layer 3 ----
    aggregate64_kernel<<<AB, 256>>>(rp, er0, er1, h1, zb);
    gemmsum_kernel<64><<<GB, 256, SM64>>>(zb, W3, b3, h0);
    // ---- layer 4 ----
    aggregate64_kernel<<<AB, 256>>>(rp, er0, er1, h0, zb);
    gemmsum_kernel<64><<<GB, 256, SM64>>>(zb, W4, b4, h1);

    pool_kernel<<<Gg, 256>>>(h1, pl);
    head_kernel<<<Gg, 32>>>(pl, bng, bnb, bnm, bnv, fw, fb, out);
}

// round 16
// speedup vs baseline: 1.0280x; 1.0280x over previous
#include <cuda_runtime.h>
#include <cstdint>
#include <cstddef>

#define Nn 50000
#define Ee 1600000
#define Gg 128
#define Hh 64

// ---- scratch (device globals) ----
__device__ uint32_t g_z[(size_t)5 * Nn * Hh]; // 64 MB: z_k as tf32 bits
__device__ float g_h0[(size_t)Nn * Hh];        // ping
__device__ float g_h1[(size_t)Nn * Hh];        // pong
__device__ float g_pool[Gg * 2 * Hh];

// dst-CSR sort scratch (24 B/edge, split)
__device__ int    g_cnt[Nn];
__device__ int    g_cursor[Nn];
__device__ int    g_rowptr[Nn + 1];
__device__ float4 g_er0[Ee];                   // {src, w0, w1, w2}
__device__ float2 g_er1[Ee];                   // {w3, w4}

__device__ __forceinline__ uint32_t to_tf32(float v)
{
    uint32_t u;
    asm("cvt.rna.tf32.f32 %0, %1;" : "=r"(u) : "f"(v));
    return u;
}

// ============================================================
// counting sort by dst: hist -> scan -> permute
// ============================================================
__global__ void zero_cnt_kernel(int* __restrict__ cnt)
{
    unsigned i = blockIdx.x * 256u + threadIdx.x;
    if (i < (unsigned)Nn) cnt[i] = 0;
}

__global__ void hist_kernel(const int* __restrict__ ei, int* __restrict__ cnt)
{
    unsigned e = blockIdx.x * 256u + threadIdx.x;
    if (e < (unsigned)Ee) atomicAdd(&cnt[__ldg(ei + Ee + e)], 1);  // dst
}

__global__ void scan_kernel(const int* __restrict__ cnt,
                            int* __restrict__ cursor,
                            int* __restrict__ rowptr)
{
    __shared__ int tsum[1024];
    const int t  = threadIdx.x;
    const int CH = (Nn + 1023) / 1024;  // 49
    const int base = t * CH;

    int s = 0;
#pragma unroll 1
    for (int i = 0; i < CH; ++i) {
        int idx = base + i;
        if (idx < Nn) s += cnt[idx];
    }
    tsum[t] = s;
    __syncthreads();
    for (int o = 1; o < 1024; o <<= 1) {
        int u = (t >= o) ? tsum[t - o] : 0;
        __syncthreads();
        tsum[t] += u;
        __syncthreads();
    }
    int run = tsum[t] - s;  // exclusive
#pragma unroll 1
    for (int i = 0; i < CH; ++i) {
        int idx = base + i;
        if (idx < Nn) {
            cursor[idx] = run;
            rowptr[idx] = run;
            run += cnt[idx];
        }
    }
    if (t == 0) rowptr[Nn] = Ee;
}

__global__ void permute_kernel(const int* __restrict__ ei,
                               const float* __restrict__ ea,
                               int* __restrict__ cursor,
                               float4* __restrict__ er0,
                               float2* __restrict__ er1)
{
    unsigned e = blockIdx.x * 256u + threadIdx.x;
    if (e >= (unsigned)Ee) return;
    int src = __ldg(ei + e);
    int dst = __ldg(ei + Ee + e);
    const float* p = ea + (size_t)e * 5;
    float w0 = __ldg(p), w1 = __ldg(p + 1), w2 = __ldg(p + 2),
          w3 = __ldg(p + 3), w4 = __ldg(p + 4);
    int pos = atomicAdd(&cursor[dst], 1);
    er0[pos] = make_float4(__int_as_float(src), w0, w1, w2);
    er1[pos] = make_float2(w3, w4);
}

// ============================================================
// Aggregate (H=64): one warp per dst node; 2 edges in flight.
// Epilogue converts accumulators to tf32 bits for the MMA gemm.
// ============================================================
__global__ void aggregate64_kernel(const int* __restrict__ rowptr,
                                   const float4* __restrict__ er0,
                                   const float2* __restrict__ er1,
                                   const float* __restrict__ x,
                                   uint32_t* __restrict__ z)
{
    int dst = blockIdx.x * 8 + (threadIdx.x >> 5);
    if (dst >= Nn) return;
    const int lane = threadIdx.x & 31;
    const int hl   = lane & 15;   // feat group: feats 4*hl..4*hl+3
    const int par  = lane >> 4;   // edge parity
    const int beg = __ldg(rowptr + dst);
    const int end = __ldg(rowptr + dst + 1);

    float4 a0 = {0.f,0.f,0.f,0.f}, a1 = a0, a2 = a0, a3 = a0, a4 = a0;

#pragma unroll 2
    for (int e = beg + par; e < end; e += 2) {
        float4 r0 = __ldg(er0 + e);
        float2 r1 = __ldg(er1 + e);
        int src = __float_as_int(r0.x);
        float4 v = __ldg((const float4*)(x + (size_t)src * 64 + hl * 4));
        a0.x += r0.y*v.x; a0.y += r0.y*v.y; a0.z += r0.y*v.z; a0.w += r0.y*v.w;
        a1.x += r0.z*v.x; a1.y += r0.z*v.y; a1.z += r0.z*v.z; a1.w += r0.z*v.w;
        a2.x += r0.w*v.x; a2.y += r0.w*v.y; a2.z += r0.w*v.z; a2.w += r0.w*v.w;
        a3.x += r1.x*v.x; a3.y += r1.x*v.y; a3.z += r1.x*v.z; a3.w += r1.x*v.w;
        a4.x += r1.y*v.x; a4.y += r1.y*v.y; a4.z += r1.y*v.z; a4.w += r1.y*v.w;
    }

#define CMB(f) f += __shfl_xor_sync(0xffffffffu, f, 16)
    CMB(a0.x); CMB(a0.y); CMB(a0.z); CMB(a0.w);
    CMB(a1.x); CMB(a1.y); CMB(a1.z); CMB(a1.w);
    CMB(a2.x); CMB(a2.y); CMB(a2.z); CMB(a2.w);
    CMB(a3.x); CMB(a3.y); CMB(a3.z); CMB(a3.w);
    CMB(a4.x); CMB(a4.y); CMB(a4.z); CMB(a4.w);
#undef CMB

    if (par == 0) {
        const size_t KS = (size_t)Nn * 64;
        uint32_t* zp = z + (size_t)dst * 64 + hl * 4;
#define STT(off, a) { uint4 q; q.x = to_tf32(a.x); q.y = to_tf32(a.y); \
                      q.z = to_tf32(a.z); q.w = to_tf32(a.w); \
                      *(uint4*)(zp + (off)) = q; }
        STT(0,      a0)
        STT(KS,     a1)
        STT(2 * KS, a2)
        STT(3 * KS, a3)
        STT(4 * KS, a4)
#undef STT
    }
}

// ============================================================
// Aggregate (F=16, layer 1, raw x)
// ============================================================
__global__ void aggregate16_kernel(const int* __restrict__ rowptr,
                                   const float4* __restrict__ er0,
                                   const float2* __restrict__ er1,
                                   const float* __restrict__ x,
                                   uint32_t* __restrict__ z)
{
    int dst = blockIdx.x * 8 + (threadIdx.x >> 5);
    if (dst >= Nn) return;
    const int lane = threadIdx.x & 31;
    const int half = lane >> 4;
    const int f    = lane & 15;
    const int beg = __ldg(rowptr + dst);
    const int end = __ldg(rowptr + dst + 1);

    float a0 = 0.f, a1 = 0.f, a2 = 0.f, a3 = 0.f, a4 = 0.f;

    for (int e = beg + half; e < end; e += 2) {
        float4 r0 = __ldg(er0 + e);
        float2 r1 = __ldg(er1 + e);
        int src = __float_as_int(r0.x);
        float v = __ldg(x + (size_t)src * 16 + f);
        a0 += r0.y * v; a1 += r0.z * v; a2 += r0.w * v;
        a3 += r1.x * v; a4 += r1.y * v;
    }
    a0 += __shfl_xor_sync(0xffffffffu, a0, 16);
    a1 += __shfl_xor_sync(0xffffffffu, a1, 16);
    a2 += __shfl_xor_sync(0xffffffffu, a2, 16);
    a3 += __shfl_xor_sync(0xffffffffu, a3, 16);
    a4 += __shfl_xor_sync(0xffffffffu, a4, 16);

    if (half == 0) {
        const size_t KS = (size_t)Nn * 16;
        uint32_t* zp = z + (size_t)dst * 16 + f;
        zp[0]    = to_tf32(a0);
        zp[KS]   = to_tf32(a1);
        zp[2*KS] = to_tf32(a2);
        zp[3*KS] = to_tf32(a3);
        zp[4*KS] = to_tf32(a4);
    }
}

// ============================================================
// Tensor-core GEMM-sum: h[n] = relu( sum_k z_k[n] @ W[k] + b )
// mma.sync.m16n8k8 tf32. 128 nodes x 64 cols / CTA, 8 warps,
// warp tile 32x32 (round-14 structure). z arrives pre-converted
// tf32 bits, so A staging is a pure u32 copy (no cvt).
// smem: zs[128][ZPAD] + ws[KD][72] u32; KD=64: 53.2 KB -> 4 CTAs/SM.
// ============================================================
template<int KD>
__global__ void __launch_bounds__(256, 4)
gemmsum_kernel(const uint32_t* __restrict__ zq,
               const float* __restrict__ W,
               const float* __restrict__ b,
               float* __restrict__ h)
{
    constexpr int ZPAD = (KD == 64) ? 68 : 20;
    constexpr int WPAD = 72;
    extern __shared__ uint32_t smu[];
    uint32_t* zs = smu;                 // [128][ZPAD] tf32 bits
    uint32_t* ws = smu + 128 * ZPAD;    // [KD][WPAD]  tf32 bits

    const int t    = threadIdx.x;
    const int warp = t >> 5;
    const int lane = t & 31;
    const int gid  = lane >> 2;    // 0..7
    const int tig  = lane & 3;     // 0..3
    const int wm   = warp >> 1;    // 0..3 -> m offset 32*wm
    const int wn   = warp & 1;     // 0..1 -> n offset 32*wn
    const int n0   = blockIdx.x * 128;

    float acc[2][4][4];
#pragma unroll
    for (int mf = 0; mf < 2; ++mf)
#pragma unroll
        for (int nf = 0; nf < 4; ++nf)
#pragma unroll
            for (int r = 0; r < 4; ++r) acc[mf][nf][r] = 0.f;

#pragma unroll 1
    for (int k = 0; k < 5; ++k) {
        __syncthreads();
        const uint32_t* zk = zq + (size_t)k * Nn * KD;
        for (int idx = t; idx < 128 * KD; idx += 256) {
            int node = idx / KD;
            int c    = idx - node * KD;
            int n    = n0 + node;
            zs[node * ZPAD + c] = (n < Nn) ? __ldg(zk + (size_t)n * KD + c) : 0u;
        }
        for (int idx = t; idx < KD * 64; idx += 256) {
            float v = __ldg(W + k * KD * 64 + idx);
            int kk = idx >> 6;
            int c  = idx & 63;
            ws[kk * WPAD + c] = to_tf32(v);
        }
        __syncthreads();

#pragma unroll
        for (int kb = 0; kb < KD; kb += 8) {
            uint32_t a[2][4];
#pragma unroll
            for (int mf = 0; mf < 2; ++mf) {
                int row = wm * 32 + mf * 16 + gid;
                a[mf][0] = zs[row * ZPAD + kb + tig];
                a[mf][1] = zs[(row + 8) * ZPAD + kb + tig];
                a[mf][2] = zs[row * ZPAD + kb + tig + 4];
                a[mf][3] = zs[(row + 8) * ZPAD + kb + tig + 4];
            }
            uint32_t bf[4][2];
#pragma unroll
            for (int nf = 0; nf < 4; ++nf) {
                int col = wn * 32 + nf * 8 + gid;
                bf[nf][0] = ws[(kb + tig) * WPAD + col];
                bf[nf][1] = ws[(kb + tig + 4) * WPAD + col];
            }
#pragma unroll
            for (int mf = 0; mf < 2; ++mf)
#pragma unroll
                for (int nf = 0; nf < 4; ++nf) {
                    asm volatile(
                        "mma.sync.aligned.m16n8k8.row.col.f32.tf32.tf32.f32 "
                        "{%0,%1,%2,%3}, {%4,%5,%6,%7}, {%8,%9}, {%0,%1,%2,%3};"
                        : "+f"(acc[mf][nf][0]), "+f"(acc[mf][nf][1]),
                          "+f"(acc[mf][nf][2]), "+f"(acc[mf][nf][3])
                        : "r"(a[mf][0]), "r"(a[mf][1]), "r"(a[mf][2]), "r"(a[mf][3]),
                          "r"(bf[nf][0]), "r"(bf[nf][1]));
                }
        }
    }

    // epilogue: bias + relu + store
#pragma unroll
    for (int mf = 0; mf < 2; ++mf) {
#pragma unroll
        for (int nf = 0; nf < 4; ++nf) {
            int col = wn * 32 + nf * 8 + 2 * tig;
            float bx = __ldg(b + col);
            float by = __ldg(b + col + 1);
            int row = n0 + wm * 32 + mf * 16 + gid;
            if (row < Nn) {
                float2 o;
                o.x = fmaxf(acc[mf][nf][0] + bx, 0.f);
                o.y = fmaxf(acc[mf][nf][1] + by, 0.f);
                *(float2*)&h[(size_t)row * 64 + col] = o;
            }
            int row2 = row + 8;
            if (row2 < Nn) {
                float2 o;
                o.x = fmaxf(acc[mf][nf][2] + bx, 0.f);
                o.y = fmaxf(acc[mf][nf][3] + by, 0.f);
                *(float2*)&h[(size_t)row2 * 64 + col] = o;
            }
        }
    }
}

// ============================================================
// Pooling: h already relu'd; sum & max per analytic graph ranges.
// ============================================================
__global__ void pool_kernel(const float* __restrict__ h, float* __restrict__ pooled)
{
    __shared__ float ss[4][64];
    __shared__ float sm[4][64];
    int g     = blockIdx.x;
    int f     = threadIdx.x & 63;
    int strip = threadIdx.x >> 6;
    int start = (g * Nn + Gg - 1) / Gg;
    int end   = ((g + 1) * Nn + Gg - 1) / Gg;

    float s = 0.f, m = 0.f;  // h >= 0
    for (int n = start + strip; n < end; n += 4) {
        float v = __ldg(h + (size_t)n * 64 + f);
        s += v;
        m = fmaxf(m, v);
    }
    ss[strip][f] = s;
    sm[strip][f] = m;
    __syncthreads();
    if (strip == 0) {
        s = ss[0][f] + ss[1][f] + ss[2][f] + ss[3][f];
        m = fmaxf(fmaxf(sm[0][f], sm[1][f]), fmaxf(sm[2][f], sm[3][f]));
        pooled[g * 128 + f]      = s;
        pooled[g * 128 + 64 + f] = m;
    }
}

// ============================================================
// Head: BN -> FC -> log_softmax
// ============================================================
__global__ void head_kernel(const float* __restrict__ pooled,
                            const float* __restrict__ gam,
                            const float* __restrict__ bet,
                            const float* __restrict__ mean,
                            const float* __restrict__ var,
                            const float* __restrict__ fw,
                            const float* __restrict__ fb,
                            float* __restrict__ out)
{
    int g    = blockIdx.x;
    int lane = threadIdx.x;

    float pn[4];
#pragma unroll
    for (int i = 0; i < 4; ++i) {
        int c = lane + 32 * i;
        float p = __ldg(pooled + g * 128 + c);
        float inv = 1.f / sqrtf(__ldg(var + c) + 1e-5f);
        pn[i] = (p - __ldg(mean + c)) * inv * __ldg(gam + c) + __ldg(bet + c);
    }

    float logits[6];
#pragma unroll
    for (int j = 0; j < 6; ++j) {
        float s = 0.f;
#pragma unroll
        for (int i = 0; i < 4; ++i)
            s += pn[i] * __ldg(fw + (lane + 32 * i) * 6 + j);
#pragma unroll
        for (int o = 16; o; o >>= 1)
            s += __shfl_xor_sync(0xffffffffu, s, o);
        logits[j] = s + __ldg(fb + j);
    }

    if (lane == 0) {
        float m = logits[0];
#pragma unroll
        for (int j = 1; j < 6; ++j) m = fmaxf(m, logits[j]);
        float se = 0.f;
#pragma unroll
        for (int j = 0; j < 6; ++j) se += expf(logits[j] - m);
        float lse = m + logf(se);
#pragma unroll
        for (int j = 0; j < 6; ++j) out[g * 6 + j] = logits[j] - lse;
    }
}

// ============================================================
extern "C" void kernel_launch(void* const* d_in, const int* in_sizes, int n_in,
                              void* d_out, int out_size)
{
    const float* x   = (const float*)d_in[0];
    const int*   ei  = (const int*)  d_in[1];
    const float* ea  = (const float*)d_in[2];
    const float* W1  = (const float*)d_in[4];
    const float* b1  = (const float*)d_in[5];
    const float* W2  = (const float*)d_in[6];
    const float* b2  = (const float*)d_in[7];
    const float* W3  = (const float*)d_in[8];
    const float* b3  = (const float*)d_in[9];
    const float* W4  = (const float*)d_in[10];
    const float* b4  = (const float*)d_in[11];
    const float* bng = (const float*)d_in[12];
    const float* bnb = (const float*)d_in[13];
    const float* bnm = (const float*)d_in[14];
    const float* bnv = (const float*)d_in[15];
    const float* fw  = (const float*)d_in[16];
    const float* fb  = (const float*)d_in[17];
    float* out = (float*)d_out;

    uint32_t* zb;
    float *h0, *h1, *pl;
    int *cnt, *cur, *rp;
    float4* er0;
    float2* er1;
    cudaGetSymbolAddress((void**)&zb, g_z);
    cudaGetSymbolAddress((void**)&h0, g_h0);
    cudaGetSymbolAddress((void**)&h1, g_h1);
    cudaGetSymbolAddress((void**)&pl, g_pool);
    cudaGetSymbolAddress((void**)&cnt, g_cnt);
    cudaGetSymbolAddress((void**)&cur, g_cursor);
    cudaGetSymbolAddress((void**)&rp, g_rowptr);
    cudaGetSymbolAddress((void**)&er0, g_er0);
    cudaGetSymbolAddress((void**)&er1, g_er1);

    const int EB = (Ee + 255) / 256;        // 6250
    const int GB = (Nn + 127) / 128;        // 391
    const int AB = (Nn + 7) / 8;            // 6250 (one warp per dst)

    const int SM16 = (128 * 20 + 16 * 72) * 4;   // 14848 B
    const int SM64 = (128 * 68 + 64 * 72) * 4;   // 53248 B
    static int smem_set = 0;
    if (!smem_set) {
        cudaFuncSetAttribute(gemmsum_kernel<16>, cudaFuncAttributeMaxDynamicSharedMemorySize, SM16);
        cudaFuncSetAttribute(gemmsum_kernel<64>, cudaFuncAttributeMaxDynamicSharedMemorySize, SM64);
        smem_set = 1;
    }

    // ---- counting sort of edges by dst -> CSR ----
    zero_cnt_kernel<<<(Nn + 255) / 256, 256>>>(cnt);
    hist_kernel<<<EB, 256>>>(ei, cnt);
    scan_kernel<<<1, 1024>>>(cnt, cur, rp);
    permute_kernel<<<EB, 256>>>(ei, ea, cur, er0, er1);

    // ---- layer 1 (in: x [N,16], raw) ----
    aggregate16_kernel<<<AB, 256>>>(rp, er0, er1, x, zb);
    gemmsum_kernel<16><<<GB, 256, SM16>>>(zb, W1, b1, h0);
    // ---- layer 2 ----
    aggregate64_kernel<<<AB, 256>>>(rp, er0, er1, h0, zb);
    gemmsum_kernel<64><<<GB, 256, SM64>>>(zb, W2, b2, h1);
    // ---- layer 3 ----
    aggregate64_kernel<<<AB, 256>>>(rp, er0, er1, h1, zb);
    gemmsum_kernel<64><<<GB, 256, SM64>>>(zb, W3, b3, h0);
    // ---- layer 4 ----
    aggregate64_kernel<<<AB, 256>>>(rp, er0, er1, h0, zb);
    gemmsum_kernel<64><<<GB, 256, SM64>>>(zb, W4, b4, h1);

    pool_kernel<<<Gg, 256>>>(h1, pl);
    head_kernel<<<Gg, 32>>>(pl, bng, bnb, bnm, bnv, fw, fb, out);
}

// round 17
// speedup vs baseline: 1.1007x; 1.0707x over previous
#include <cuda_runtime.h>
#include <cstdint>
#include <cstddef>

#define Nn 50000
#define Ee 1600000
#define Gg 128
#define Hh 64

// ---- scratch (device globals) ----
__device__ uint32_t g_z[(size_t)5 * Nn * Hh]; // 64 MB: z_k as tf32 bits
__device__ float g_h0[(size_t)Nn * Hh];        // ping
__device__ float g_h1[(size_t)Nn * Hh];        // pong
__device__ float g_pool[Gg * 2 * Hh];

// dst-CSR sort scratch (24 B/edge, split)
__device__ int    g_cnt[Nn];
__device__ int    g_cursor[Nn];
__device__ int    g_rowptr[Nn + 1];
__device__ float4 g_er0[Ee];                   // {src, w0, w1, w2}
__device__ float2 g_er1[Ee];                   // {w3, w4}

__device__ __forceinline__ uint32_t to_tf32(float v)
{
    uint32_t u;
    asm("cvt.rna.tf32.f32 %0, %1;" : "=r"(u) : "f"(v));
    return u;
}

// ============================================================
// counting sort by dst: hist -> scan -> permute
// ============================================================
__global__ void zero_cnt_kernel(int* __restrict__ cnt)
{
    unsigned i = blockIdx.x * 256u + threadIdx.x;
    if (i < (unsigned)Nn) cnt[i] = 0;
}

__global__ void hist_kernel(const int* __restrict__ ei, int* __restrict__ cnt)
{
    unsigned e = blockIdx.x * 256u + threadIdx.x;
    if (e < (unsigned)Ee) atomicAdd(&cnt[__ldg(ei + Ee + e)], 1);  // dst
}

__global__ void scan_kernel(const int* __restrict__ cnt,
                            int* __restrict__ cursor,
                            int* __restrict__ rowptr)
{
    __shared__ int tsum[1024];
    const int t  = threadIdx.x;
    const int CH = (Nn + 1023) / 1024;  // 49
    const int base = t * CH;

    int s = 0;
#pragma unroll 1
    for (int i = 0; i < CH; ++i) {
        int idx = base + i;
        if (idx < Nn) s += cnt[idx];
    }
    tsum[t] = s;
    __syncthreads();
    for (int o = 1; o < 1024; o <<= 1) {
        int u = (t >= o) ? tsum[t - o] : 0;
        __syncthreads();
        tsum[t] += u;
        __syncthreads();
    }
    int run = tsum[t] - s;  // exclusive
#pragma unroll 1
    for (int i = 0; i < CH; ++i) {
        int idx = base + i;
        if (idx < Nn) {
            cursor[idx] = run;
            rowptr[idx] = run;
            run += cnt[idx];
        }
    }
    if (t == 0) rowptr[Nn] = Ee;
}

__global__ void permute_kernel(const int* __restrict__ ei,
                               const float* __restrict__ ea,
                               int* __restrict__ cursor,
                               float4* __restrict__ er0,
                               float2* __restrict__ er1)
{
    unsigned e = blockIdx.x * 256u + threadIdx.x;
    if (e >= (unsigned)Ee) return;
    int src = __ldg(ei + e);
    int dst = __ldg(ei + Ee + e);
    const float* p = ea + (size_t)e * 5;
    float w0 = __ldg(p), w1 = __ldg(p + 1), w2 = __ldg(p + 2),
          w3 = __ldg(p + 3), w4 = __ldg(p + 4);
    int pos = atomicAdd(&cursor[dst], 1);
    er0[pos] = make_float4(__int_as_float(src), w0, w1, w2);
    er1[pos] = make_float2(w3, w4);
}

// ============================================================
// Aggregate (H=64): one warp per dst node; 2 edges in flight.
// Epilogue converts accumulators to tf32 bits for the MMA gemm.
// ============================================================
__global__ void aggregate64_kernel(const int* __restrict__ rowptr,
                                   const float4* __restrict__ er0,
                                   const float2* __restrict__ er1,
                                   const float* __restrict__ x,
                                   uint32_t* __restrict__ z)
{
    int dst = blockIdx.x * 8 + (threadIdx.x >> 5);
    if (dst >= Nn) return;
    const int lane = threadIdx.x & 31;
    const int hl   = lane & 15;   // feat group: feats 4*hl..4*hl+3
    const int par  = lane >> 4;   // edge parity
    const int beg = __ldg(rowptr + dst);
    const int end = __ldg(rowptr + dst + 1);

    float4 a0 = {0.f,0.f,0.f,0.f}, a1 = a0, a2 = a0, a3 = a0, a4 = a0;

#pragma unroll 2
    for (int e = beg + par; e < end; e += 2) {
        float4 r0 = __ldg(er0 + e);
        float2 r1 = __ldg(er1 + e);
        int src = __float_as_int(r0.x);
        float4 v = __ldg((const float4*)(x + (size_t)src * 64 + hl * 4));
        a0.x += r0.y*v.x; a0.y += r0.y*v.y; a0.z += r0.y*v.z; a0.w += r0.y*v.w;
        a1.x += r0.z*v.x; a1.y += r0.z*v.y; a1.z += r0.z*v.z; a1.w += r0.z*v.w;
        a2.x += r0.w*v.x; a2.y += r0.w*v.y; a2.z += r0.w*v.z; a2.w += r0.w*v.w;
        a3.x += r1.x*v.x; a3.y += r1.x*v.y; a3.z += r1.x*v.z; a3.w += r1.x*v.w;
        a4.x += r1.y*v.x; a4.y += r1.y*v.y; a4.z += r1.y*v.z; a4.w += r1.y*v.w;
    }

#define CMB(f) f += __shfl_xor_sync(0xffffffffu, f, 16)
    CMB(a0.x); CMB(a0.y); CMB(a0.z); CMB(a0.w);
    CMB(a1.x); CMB(a1.y); CMB(a1.z); CMB(a1.w);
    CMB(a2.x); CMB(a2.y); CMB(a2.z); CMB(a2.w);
    CMB(a3.x); CMB(a3.y); CMB(a3.z); CMB(a3.w);
    CMB(a4.x); CMB(a4.y); CMB(a4.z); CMB(a4.w);
#undef CMB

    if (par == 0) {
        const size_t KS = (size_t)Nn * 64;
        uint32_t* zp = z + (size_t)dst * 64 + hl * 4;
#define STT(off, a) { uint4 q; q.x = to_tf32(a.x); q.y = to_tf32(a.y); \
                      q.z = to_tf32(a.z); q.w = to_tf32(a.w); \
                      *(uint4*)(zp + (off)) = q; }
        STT(0,      a0)
        STT(KS,     a1)
        STT(2 * KS, a2)
        STT(3 * KS, a3)
        STT(4 * KS, a4)
#undef STT
    }
}

// ============================================================
// Aggregate (F=16, layer 1, raw x)
// ============================================================
__global__ void aggregate16_kernel(const int* __restrict__ rowptr,
                                   const float4* __restrict__ er0,
                                   const float2* __restrict__ er1,
                                   const float* __restrict__ x,
                                   uint32_t* __restrict__ z)
{
    int dst = blockIdx.x * 8 + (threadIdx.x >> 5);
    if (dst >= Nn) return;
    const int lane = threadIdx.x & 31;
    const int half = lane >> 4;
    const int f    = lane & 15;
    const int beg = __ldg(rowptr + dst);
    const int end = __ldg(rowptr + dst + 1);

    float a0 = 0.f, a1 = 0.f, a2 = 0.f, a3 = 0.f, a4 = 0.f;

    for (int e = beg + half; e < end; e += 2) {
        float4 r0 = __ldg(er0 + e);
        float2 r1 = __ldg(er1 + e);
        int src = __float_as_int(r0.x);
        float v = __ldg(x + (size_t)src * 16 + f);
        a0 += r0.y * v; a1 += r0.z * v; a2 += r0.w * v;
        a3 += r1.x * v; a4 += r1.y * v;
    }
    a0 += __shfl_xor_sync(0xffffffffu, a0, 16);
    a1 += __shfl_xor_sync(0xffffffffu, a1, 16);
    a2 += __shfl_xor_sync(0xffffffffu, a2, 16);
    a3 += __shfl_xor_sync(0xffffffffu, a3, 16);
    a4 += __shfl_xor_sync(0xffffffffu, a4, 16);

    if (half == 0) {
        const size_t KS = (size_t)Nn * 16;
        uint32_t* zp = z + (size_t)dst * 16 + f;
        zp[0]    = to_tf32(a0);
        zp[KS]   = to_tf32(a1);
        zp[2*KS] = to_tf32(a2);
        zp[3*KS] = to_tf32(a3);
        zp[4*KS] = to_tf32(a4);
    }
}

// ============================================================
// Tensor-core GEMM-sum: h[n] = relu( sum_k z_k[n] @ W[k] + b )
// mma.sync.m16n8k8 tf32. 128 nodes x 64 cols / CTA, 8 warps,
// warp tile 32x32. z arrives pre-converted tf32 bits; staging
// loops use 128-bit loads/stores (uint4/float4).
// smem: zs[128][ZPAD] + ws[KD][72] u32; KD=64: 53.2 KB -> 4 CTAs/SM.
// ZPAD/WPAD rows are 16B-aligned (68*4=272=17*16, 72*4=288=18*16).
// ============================================================
template<int KD>
__global__ void __launch_bounds__(256, 4)
gemmsum_kernel(const uint32_t* __restrict__ zq,
               const float* __restrict__ W,
               const float* __restrict__ b,
               float* __restrict__ h)
{
    constexpr int ZPAD = (KD == 64) ? 68 : 20;
    constexpr int WPAD = 72;
    constexpr int KD4  = KD / 4;
    extern __shared__ uint32_t smu[];
    uint32_t* zs = smu;                 // [128][ZPAD] tf32 bits
    uint32_t* ws = smu + 128 * ZPAD;    // [KD][WPAD]  tf32 bits

    const int t    = threadIdx.x;
    const int warp = t >> 5;
    const int lane = t & 31;
    const int gid  = lane >> 2;    // 0..7
    const int tig  = lane & 3;     // 0..3
    const int wm   = warp >> 1;    // 0..3 -> m offset 32*wm
    const int wn   = warp & 1;     // 0..1 -> n offset 32*wn
    const int n0   = blockIdx.x * 128;

    float acc[2][4][4];
#pragma unroll
    for (int mf = 0; mf < 2; ++mf)
#pragma unroll
        for (int nf = 0; nf < 4; ++nf)
#pragma unroll
            for (int r = 0; r < 4; ++r) acc[mf][nf][r] = 0.f;

#pragma unroll 1
    for (int k = 0; k < 5; ++k) {
        __syncthreads();
        const uint32_t* zk = zq + (size_t)k * Nn * KD;
        // z staging: 128*KD/4 uint4 transfers
        for (int idx = t; idx < 128 * KD4; idx += 256) {
            int node = idx / KD4;
            int c4   = idx - node * KD4;
            int n    = n0 + node;
            uint4 q = (n < Nn) ? __ldg((const uint4*)(zk + (size_t)n * KD + c4 * 4))
                               : make_uint4(0u, 0u, 0u, 0u);
            *(uint4*)&zs[node * ZPAD + c4 * 4] = q;
        }
        // W staging: KD*16 float4 loads + cvt + uint4 stores
        for (int idx = t; idx < KD * 16; idx += 256) {
            int kk = idx >> 4;
            int c4 = idx & 15;
            float4 v = __ldg((const float4*)(W + k * KD * 64 + kk * 64 + c4 * 4));
            uint4 q;
            q.x = to_tf32(v.x); q.y = to_tf32(v.y);
            q.z = to_tf32(v.z); q.w = to_tf32(v.w);
            *(uint4*)&ws[kk * WPAD + c4 * 4] = q;
        }
        __syncthreads();

#pragma unroll
        for (int kb = 0; kb < KD; kb += 8) {
            uint32_t a[2][4];
#pragma unroll
            for (int mf = 0; mf < 2; ++mf) {
                int row = wm * 32 + mf * 16 + gid;
                a[mf][0] = zs[row * ZPAD + kb + tig];
                a[mf][1] = zs[(row + 8) * ZPAD + kb + tig];
                a[mf][2] = zs[row * ZPAD + kb + tig + 4];
                a[mf][3] = zs[(row + 8) * ZPAD + kb + tig + 4];
            }
            uint32_t bf[4][2];
#pragma unroll
            for (int nf = 0; nf < 4; ++nf) {
                int col = wn * 32 + nf * 8 + gid;
                bf[nf][0] = ws[(kb + tig) * WPAD + col];
                bf[nf][1] = ws[(kb + tig + 4) * WPAD + col];
            }
#pragma unroll
            for (int mf = 0; mf < 2; ++mf)
#pragma unroll
                for (int nf = 0; nf < 4; ++nf) {
                    asm volatile(
                        "mma.sync.aligned.m16n8k8.row.col.f32.tf32.tf32.f32 "
                        "{%0,%1,%2,%3}, {%4,%5,%6,%7}, {%8,%9}, {%0,%1,%2,%3};"
                        : "+f"(acc[mf][nf][0]), "+f"(acc[mf][nf][1]),
                          "+f"(acc[mf][nf][2]), "+f"(acc[mf][nf][3])
                        : "r"(a[mf][0]), "r"(a[mf][1]), "r"(a[mf][2]), "r"(a[mf][3]),
                          "r"(bf[nf][0]), "r"(bf[nf][1]));
                }
        }
    }

    // epilogue: bias + relu + store
#pragma unroll
    for (int mf = 0; mf < 2; ++mf) {
#pragma unroll
        for (int nf = 0; nf < 4; ++nf) {
            int col = wn * 32 + nf * 8 + 2 * tig;
            float bx = __ldg(b + col);
            float by = __ldg(b + col + 1);
            int row = n0 + wm * 32 + mf * 16 + gid;
            if (row < Nn) {
                float2 o;
                o.x = fmaxf(acc[mf][nf][0] + bx, 0.f);
                o.y = fmaxf(acc[mf][nf][1] + by, 0.f);
                *(float2*)&h[(size_t)row * 64 + col] = o;
            }
            int row2 = row + 8;
            if (row2 < Nn) {
                float2 o;
                o.x = fmaxf(acc[mf][nf][2] + bx, 0.f);
                o.y = fmaxf(acc[mf][nf][3] + by, 0.f);
                *(float2*)&h[(size_t)row2 * 64 + col] = o;
            }
        }
    }
}

// ============================================================
// Pooling: h already relu'd; sum & max per analytic graph ranges.
// ============================================================
__global__ void pool_kernel(const float* __restrict__ h, float* __restrict__ pooled)
{
    __shared__ float ss[4][64];
    __shared__ float sm[4][64];
    int g     = blockIdx.x;
    int f     = threadIdx.x & 63;
    int strip = threadIdx.x >> 6;
    int start = (g * Nn + Gg - 1) / Gg;
    int end   = ((g + 1) * Nn + Gg - 1) / Gg;

    float s = 0.f, m = 0.f;  // h >= 0
    for (int n = start + strip; n < end; n += 4) {
        float v = __ldg(h + (size_t)n * 64 + f);
        s += v;
        m = fmaxf(m, v);
    }
    ss[strip][f] = s;
    sm[strip][f] = m;
    __syncthreads();
    if (strip == 0) {
        s = ss[0][f] + ss[1][f] + ss[2][f] + ss[3][f];
        m = fmaxf(fmaxf(sm[0][f], sm[1][f]), fmaxf(sm[2][f], sm[3][f]));
        pooled[g * 128 + f]      = s;
        pooled[g * 128 + 64 + f] = m;
    }
}

// ============================================================
// Head: BN -> FC -> log_softmax
// ============================================================
__global__ void head_kernel(const float* __restrict__ pooled,
                            const float* __restrict__ gam,
                            const float* __restrict__ bet,
                            const float* __restrict__ mean,
                            const float* __restrict__ var,
                            const float* __restrict__ fw,
                            const float* __restrict__ fb,
                            float* __restrict__ out)
{
    int g    = blockIdx.x;
    int lane = threadIdx.x;

    float pn[4];
#pragma unroll
    for (int i = 0; i < 4; ++i) {
        int c = lane + 32 * i;
        float p = __ldg(pooled + g * 128 + c);
        float inv = 1.f / sqrtf(__ldg(var + c) + 1e-5f);
        pn[i] = (p - __ldg(mean + c)) * inv * __ldg(gam + c) + __ldg(bet + c);
    }

    float logits[6];
#pragma unroll
    for (int j = 0; j < 6; ++j) {
        float s = 0.f;
#pragma unroll
        for (int i = 0; i < 4; ++i)
            s += pn[i] * __ldg(fw + (lane + 32 * i) * 6 + j);
#pragma unroll
        for (int o = 16; o; o >>= 1)
            s += __shfl_xor_sync(0xffffffffu, s, o);
        logits[j] = s + __ldg(fb + j);
    }

    if (lane == 0) {
        float m = logits[0];
#pragma unroll
        for (int j = 1; j < 6; ++j) m = fmaxf(m, logits[j]);
        float se = 0.f;
#pragma unroll
        for (int j = 0; j < 6; ++j) se += expf(logits[j] - m);
        float lse = m + logf(se);
#pragma unroll
        for (int j = 0; j < 6; ++j) out[g * 6 + j] = logits[j] - lse;
    }
}

// ============================================================
extern "C" void kernel_launch(void* const* d_in, const int* in_sizes, int n_in,
                              void* d_out, int out_size)
{
    const float* x   = (const float*)d_in[0];
    const int*   ei  = (const int*)  d_in[1];
    const float* ea  = (const float*)d_in[2];
    const float* W1  = (const float*)d_in[4];
    const float* b1  = (const float*)d_in[5];
    const float* W2  = (const float*)d_in[6];
    const float* b2  = (const float*)d_in[7];
    const float* W3  = (const float*)d_in[8];
    const float* b3  = (const float*)d_in[9];
    const float* W4  = (const float*)d_in[10];
    const float* b4  = (const float*)d_in[11];
    const float* bng = (const float*)d_in[12];
    const float* bnb = (const float*)d_in[13];
    const float* bnm = (const float*)d_in[14];
    const float* bnv = (const float*)d_in[15];
    const float* fw  = (const float*)d_in[16];
    const float* fb  = (const float*)d_in[17];
    float* out = (float*)d_out;

    uint32_t* zb;
    float *h0, *h1, *pl;
    int *cnt, *cur, *rp;
    float4* er0;
    float2* er1;
    cudaGetSymbolAddress((void**)&zb, g_z);
    cudaGetSymbolAddress((void**)&h0, g_h0);
    cudaGetSymbolAddress((void**)&h1, g_h1);
    cudaGetSymbolAddress((void**)&pl, g_pool);
    cudaGetSymbolAddress((void**)&cnt, g_cnt);
    cudaGetSymbolAddress((void**)&cur, g_cursor);
    cudaGetSymbolAddress((void**)&rp, g_rowptr);
    cudaGetSymbolAddress((void**)&er0, g_er0);
    cudaGetSymbolAddress((void**)&er1, g_er1);

    const int EB = (Ee + 255) / 256;        // 6250
    const int GB = (Nn + 127) / 128;        // 391
    const int AB = (Nn + 7) / 8;            // 6250 (one warp per dst)

    const int SM16 = (128 * 20 + 16 * 72) * 4;   // 14848 B
    const int SM64 = (128 * 68 + 64 * 72) * 4;   // 53248 B
    static int smem_set = 0;
    if (!smem_set) {
        cudaFuncSetAttribute(gemmsum_kernel<16>, cudaFuncAttributeMaxDynamicSharedMemorySize, SM16);
        cudaFuncSetAttribute(gemmsum_kernel<64>, cudaFuncAttributeMaxDynamicSharedMemorySize, SM64);
        smem_set = 1;
    }

    // ---- counting sort of edges by dst -> CSR ----
    zero_cnt_kernel<<<(Nn + 255) / 256, 256>>>(cnt);
    hist_kernel<<<EB, 256>>>(ei, cnt);
    scan_kernel<<<1, 1024>>>(cnt, cur, rp);
    permute_kernel<<<EB, 256>>>(ei, ea, cur, er0, er1);

    // ---- layer 1 (in: x [N,16], raw) ----
    aggregate16_kernel<<<AB, 256>>>(rp, er0, er1, x, zb);
    gemmsum_kernel<16><<<GB, 256, SM16>>>(zb, W1, b1, h0);
    // ---- layer 2 ----
    aggregate64_kernel<<<AB, 256>>>(rp, er0, er1, h0, zb);
    gemmsum_kernel<64><<<GB, 256, SM64>>>(zb, W2, b2, h1);
    // ---- layer 3 ----
    aggregate64_kernel<<<AB, 256>>>(rp, er0, er1, h1, zb);
    gemmsum_kernel<64><<<GB, 256, SM64>>>(zb, W3, b3, h0);
    // ---- layer 4 ----
    aggregate64_kernel<<<AB, 256>>>(rp, er0, er1, h0, zb);
    gemmsum_kernel<64><<<GB, 256, SM64>>>(zb, W4, b4, h1);

    pool_kernel<<<Gg, 256>>>(h1, pl);
    head_kernel<<<Gg, 32>>>(pl, bng, bnb, bnm, bnv, fw, fb, out);
}